// round 3
// baseline (speedup 1.0000x reference)
#include <cuda_runtime.h>
#include <math.h>

// Problem constants
#define NROW 16384          // B*F rows
#define MTOT 65536          // NPRED * NROW

// Scratch (static device allocations — allowed)
__device__ float g_t0[MTOT * 128];   // logmap0(z_next) per (iter,row)
__device__ float g_h[MTOT * 512];    // relu(t0@W1+b1)

__device__ __forceinline__ float wsum(float v) {
#pragma unroll
    for (int o = 16; o; o >>= 1) v += __shfl_xor_sync(0xffffffffu, v, o);
    return v;
}

__device__ __forceinline__ float artanh_c(float x) {
    x = fminf(fmaxf(x, -1.0f + 1e-7f), 1.0f - 1e-7f);
    return 0.5f * logf((1.0f + x) / (1.0f - x));
}

// ---------------------------------------------------------------------------
// KA: window embedding (tan -> expmap0) + 4-step hyperbolic recurrence.
// Block = (b, group of 8 f). Warp = one (b,f) row; lane owns 4 of 128 dims.
// smem: sx[4][360][8], sw[96][128], sbias[128], sz[8][19][128], ssq[8][20]
// ---------------------------------------------------------------------------
__global__ __launch_bounds__(256, 1)
void ka_kernel(const float* __restrict__ trend, const float* __restrict__ scoar,
               const float* __restrict__ sfin,  const float* __restrict__ resid,
               const float* __restrict__ Wt, const float* __restrict__ bt,
               const float* __restrict__ Wc, const float* __restrict__ bc,
               const float* __restrict__ Wf, const float* __restrict__ bff,
               const float* __restrict__ Wr, const float* __restrict__ br,
               const float* __restrict__ alphap)
{
    extern __shared__ float sm[];
    float* sx    = sm;                    // 11520 floats
    float* sw    = sx + 11520;            // 12288 floats
    float* sbias = sw + 12288;            // 128
    float* sz    = sbias + 128;           // 8*19*128 = 19456
    float* ssq   = sz + 19456;            // 8*20 = 160

    const int tid = threadIdx.x;
    const int b   = blockIdx.x >> 4;
    const int f0  = (blockIdx.x & 15) << 3;

    // Stage inputs: last 360 time steps (segments 15..29), 8 f-columns
    {
        const float* ptrs[4] = {trend, scoar, sfin, resid};
#pragma unroll
        for (int st = 0; st < 4; ++st) {
            const float* p = ptrs[st];
            for (int idx = tid; idx < 2880; idx += 256) {
                int l = idx >> 3, f = idx & 7;
                sx[st * 2880 + idx] = p[(b * 720 + 360 + l) * 128 + f0 + f];
            }
        }
    }
    // Combined weights sw[k][d], k = stream*24+s (contiguous copies)
    for (int idx = tid; idx < 3072; idx += 256) sw[idx]        = Wt[idx];
    for (int idx = tid; idx < 3072; idx += 256) sw[3072 + idx] = Wc[idx];
    for (int idx = tid; idx < 3072; idx += 256) sw[6144 + idx] = Wf[idx];
    for (int idx = tid; idx < 3072; idx += 256) sw[9216 + idx] = Wr[idx];
    if (tid < 128) sbias[tid] = bt[tid] + bc[tid] + bff[tid] + br[tid];
    __syncthreads();

    const int w = tid >> 5, lane = tid & 31;
    const float alpha = alphap[0];
    const float4* sw4 = (const float4*)sw;
    const float4 bias4 = ((const float4*)sbias)[lane];
    float* szw  = sz + w * 19 * 128;
    float* ssqw = ssq + w * 20;

    // Build z window: z_j = expmap0(tan_j), j = 0..14
    for (int j = 0; j < 15; ++j) {
        float a0 = bias4.x, a1 = bias4.y, a2 = bias4.z, a3 = bias4.w;
#pragma unroll
        for (int st = 0; st < 4; ++st) {
            const float* sxl = sx + st * 2880 + (j * 24) * 8 + w;
#pragma unroll
            for (int s = 0; s < 24; ++s) {
                float xv = sxl[s * 8];                       // broadcast LDS
                float4 wv = sw4[(st * 24 + s) * 32 + lane];  // conflict-free LDS.128
                a0 = fmaf(xv, wv.x, a0);
                a1 = fmaf(xv, wv.y, a1);
                a2 = fmaf(xv, wv.z, a2);
                a3 = fmaf(xv, wv.w, a3);
            }
        }
        // expmap0 + project
        float n2 = wsum(a0*a0 + a1*a1 + a2*a2 + a3*a3);
        float n  = sqrtf(fmaxf(n2, 1e-12f));
        float scl = tanhf(n) / n;
        a0 *= scl; a1 *= scl; a2 *= scl; a3 *= scl;
        float yn2 = wsum(a0*a0 + a1*a1 + a2*a2 + a3*a3);
        float yn  = sqrtf(fmaxf(yn2, 1e-12f));
        if (yn > 0.99999f) {
            float ps = 0.99999f / yn;
            a0 *= ps; a1 *= ps; a2 *= ps; a3 *= ps;
            yn2 *= ps * ps;
        }
        ((float4*)(szw + j * 128))[lane] = make_float4(a0, a1, a2, a3);
        if (lane == 0) ssqw[j] = yn2;
    }
    __syncwarp();

    const float winv = 0.1f / (1.0f - powf(0.9f, 14.0f));   // 1 / sum(0.9^k, k=0..13)
    const int row = b * 128 + f0 + w;

    for (int i = 0; i < 4; ++i) {
        float av0 = 0.f, av1 = 0.f, av2 = 0.f, av3 = 0.f;
        // vel_j = logmap(z[i+j], z[i+j+1]); weighted average
        for (int j = 0; j < 14; ++j) {
            int jx = i + j;
            float4 x4 = ((const float4*)(szw + jx * 128))[lane];
            float4 y4 = ((const float4*)(szw + (jx + 1) * 128))[lane];
            float x2 = ssqw[jx], y2 = ssqw[jx + 1];
            float xy = wsum(x4.x*y4.x + x4.y*y4.y + x4.z*y4.z + x4.w*y4.w);
            // mobius_add(-x, y)
            float cA = 1.0f - 2.0f * xy + y2;        // multiplies (-x)
            float cB = 1.0f - x2;                    // multiplies y
            float iden = 1.0f / fmaxf(1.0f - 2.0f * xy + x2 * y2, 1e-6f);
            float d0 = (cB * y4.x - cA * x4.x) * iden;
            float d1 = (cB * y4.y - cA * x4.y) * iden;
            float d2 = (cB * y4.z - cA * x4.z) * iden;
            float d3 = (cB * y4.w - cA * x4.w) * iden;
            float n2 = wsum(d0*d0 + d1*d1 + d2*d2 + d3*d3);
            float n  = sqrtf(fmaxf(n2, 1e-12f));
            // (2/lam) * artanh(n) / n  with 2/lam = max(1-x2, EPS)
            float fac = fmaxf(1.0f - x2, 1e-6f) * artanh_c(n) / n;
            float wj = powf(0.9f, (float)(13 - j)) * winv;
            float t = wj * fac;
            av0 = fmaf(t, d0, av0); av1 = fmaf(t, d1, av1);
            av2 = fmaf(t, d2, av2); av3 = fmaf(t, d3, av3);
        }
        float v0 = alpha * av0, v1 = alpha * av1, v2 = alpha * av2, v3 = alpha * av3;
        // expmap(z_last, v)
        const int jl = i + 14;
        float4 xl = ((const float4*)(szw + jl * 128))[lane];
        float x2l = ssqw[jl];
        float nv2 = wsum(v0*v0 + v1*v1 + v2*v2 + v3*v3);
        float nv  = sqrtf(fmaxf(nv2, 1e-12f));
        float om  = fmaxf(1.0f - x2l, 1e-6f);
        float sscl = tanhf(nv / om) / nv;            // tanh(lam*n/2)/n
        float e0 = sscl * v0, e1 = sscl * v1, e2 = sscl * v2, e3 = sscl * v3;
        float xy = wsum(xl.x*e0 + xl.y*e1 + xl.z*e2 + xl.w*e3);
        float s2 = wsum(e0*e0 + e1*e1 + e2*e2 + e3*e3);
        float cA = 1.0f + 2.0f * xy + s2;
        float cB = 1.0f - x2l;
        float iden = 1.0f / fmaxf(1.0f + 2.0f * xy + x2l * s2, 1e-6f);
        float z0 = (cA * xl.x + cB * e0) * iden;
        float z1 = (cA * xl.y + cB * e1) * iden;
        float z2 = (cA * xl.z + cB * e2) * iden;
        float z3 = (cA * xl.w + cB * e3) * iden;
        float zn2 = wsum(z0*z0 + z1*z1 + z2*z2 + z3*z3);
        float zn  = sqrtf(fmaxf(zn2, 1e-12f));
        if (zn > 0.99999f) {
            float ps = 0.99999f / zn;
            z0 *= ps; z1 *= ps; z2 *= ps; z3 *= ps;
            zn2 *= ps * ps;
        }
        ((float4*)(szw + (i + 15) * 128))[lane] = make_float4(z0, z1, z2, z3);
        if (lane == 0) ssqw[i + 15] = zn2;
        __syncwarp();
        // t0 = logmap0(z_next)
        float tn = sqrtf(fmaxf(zn2, 1e-12f));
        float tf = artanh_c(tn) / tn;
        ((float4*)(g_t0 + (i * NROW + row) * 128))[lane] =
            make_float4(tf * z0, tf * z1, tf * z2, tf * z3);
    }
}

// ---------------------------------------------------------------------------
// KB: h = relu(t0 @ W1 + b1).  M=65536, K=128, N=512.
// Block: 64-row x 128-col tile, 256 threads, thread micro-tile 8x4.
// ---------------------------------------------------------------------------
__global__ __launch_bounds__(256, 2)
void kb_kernel(const float* __restrict__ W1, const float* __restrict__ b1)
{
    extern __shared__ float sm[];
    float* sA = sm;            // 64*128
    float* sB = sm + 64 * 128; // 128*128
    const int tid = threadIdx.x;
    const int mbase = blockIdx.x * 64;
    const int nbase = blockIdx.y * 128;

    for (int idx = tid; idx < 64 * 128; idx += 256)
        sA[idx] = g_t0[(mbase + (idx >> 7)) * 128 + (idx & 127)];
    for (int idx = tid; idx < 128 * 128; idx += 256)
        sB[idx] = W1[(idx >> 7) * 512 + nbase + (idx & 127)];
    __syncthreads();

    const int tx = tid & 31, ty = tid >> 5;
    const int r0 = ty * 8, c0 = tx * 4;
    float4 acc[8];
#pragma unroll
    for (int r = 0; r < 8; ++r) acc[r] = make_float4(0.f, 0.f, 0.f, 0.f);

    const float4* sB4 = (const float4*)sB;
#pragma unroll 8
    for (int k = 0; k < 128; ++k) {
        float4 bv = sB4[k * 32 + tx];
#pragma unroll
        for (int r = 0; r < 8; ++r) {
            float a = sA[(r0 + r) * 128 + k];   // broadcast within warp
            acc[r].x = fmaf(a, bv.x, acc[r].x);
            acc[r].y = fmaf(a, bv.y, acc[r].y);
            acc[r].z = fmaf(a, bv.z, acc[r].z);
            acc[r].w = fmaf(a, bv.w, acc[r].w);
        }
    }
    float4 bb = ((const float4*)(b1 + nbase))[tx];
#pragma unroll
    for (int r = 0; r < 8; ++r) {
        float4 h;
        h.x = fmaxf(acc[r].x + bb.x, 0.f);
        h.y = fmaxf(acc[r].y + bb.y, 0.f);
        h.z = fmaxf(acc[r].z + bb.z, 0.f);
        h.w = fmaxf(acc[r].w + bb.w, 0.f);
        ((float4*)(g_h + (mbase + r0 + r) * 512 + nbase + c0))[0] = h;
    }
}

// ---------------------------------------------------------------------------
// KC: pred = h @ W2 + b2, written directly in (b, t, f) output layout.
// Block = (iter i, batch b): 128 f-rows x 24 outputs, K=512 in 4 chunks.
// Thread: f = tid&127, s-half = tid>>7 (12 outputs each).
// ---------------------------------------------------------------------------
__global__ __launch_bounds__(256, 1)
void kc_kernel(float* __restrict__ out, const float* __restrict__ W2,
               const float* __restrict__ b2)
{
    extern __shared__ float sm[];
    float* sW2 = sm;           // 512*24 = 12288
    float* sH  = sm + 12288;   // 128*129 = 16512 (padded vs bank conflicts)
    const int tid = threadIdx.x;
    const int i = blockIdx.x;   // iter 0..3
    const int b = blockIdx.y;   // batch 0..127

    for (int idx = tid; idx < 512 * 24; idx += 256) sW2[idx] = W2[idx];

    const int f  = tid & 127;
    const int sh = tid >> 7;
    float acc[12];
#pragma unroll
    for (int j = 0; j < 12; ++j) acc[j] = 0.f;

    const int rowbase = (i * NROW + b * 128) * 512;
    for (int kc = 0; kc < 4; ++kc) {
        __syncthreads();
        for (int idx = tid; idx < 128 * 128; idx += 256) {
            int ff = idx >> 7, k = idx & 127;
            sH[ff * 129 + k] = g_h[rowbase + ff * 512 + kc * 128 + k];
        }
        __syncthreads();
#pragma unroll 4
        for (int k = 0; k < 128; ++k) {
            float hv = sH[f * 129 + k];
            const float* wrow = sW2 + (kc * 128 + k) * 24 + sh * 12;
#pragma unroll
            for (int j = 0; j < 12; ++j) acc[j] = fmaf(hv, wrow[j], acc[j]);
        }
    }
#pragma unroll
    for (int j = 0; j < 12; ++j) {
        int s = sh * 12 + j;
        out[(b * 96 + i * 24 + s) * 128 + f] = acc[j] + b2[s];
    }
}

// ---------------------------------------------------------------------------
extern "C" void kernel_launch(void* const* d_in, const int* in_sizes, int n_in,
                              void* d_out, int out_size)
{
    const float* trend = (const float*)d_in[0];
    const float* scoar = (const float*)d_in[1];
    const float* sfin  = (const float*)d_in[2];
    const float* resid = (const float*)d_in[3];
    const float* Wt = (const float*)d_in[4];
    const float* bt = (const float*)d_in[5];
    const float* Wc = (const float*)d_in[6];
    const float* bc = (const float*)d_in[7];
    const float* Wf = (const float*)d_in[8];
    const float* bf = (const float*)d_in[9];
    const float* Wr = (const float*)d_in[10];
    const float* br = (const float*)d_in[11];
    const float* alpha = (const float*)d_in[12];
    const float* W1 = (const float*)d_in[13];
    const float* b1 = (const float*)d_in[14];
    const float* W2 = (const float*)d_in[15];
    const float* b2 = (const float*)d_in[16];

    // Attribute calls execute immediately; first (non-captured) correctness
    // call sets them persistently, so repeats during capture are harmless.
    cudaFuncSetAttribute(ka_kernel, cudaFuncAttributeMaxDynamicSharedMemorySize, 174208);
    cudaFuncSetAttribute(kb_kernel, cudaFuncAttributeMaxDynamicSharedMemorySize, 98304);
    cudaFuncSetAttribute(kc_kernel, cudaFuncAttributeMaxDynamicSharedMemorySize, 115200);

    ka_kernel<<<2048, 256, 174208>>>(trend, scoar, sfin, resid,
                                     Wt, bt, Wc, bc, Wf, bf, Wr, br, alpha);
    kb_kernel<<<dim3(1024, 4), 256, 98304>>>(W1, b1);
    kc_kernel<<<dim3(4, 128), 256, 115200>>>((float*)d_out, W2, b2);
}

// round 6
// speedup vs baseline: 1.0010x; 1.0010x over previous
#include <cuda_runtime.h>
#include <math.h>

// Problem constants
#define NROW 16384          // B*F rows
#define MTOT 65536          // NPRED * NROW

// Scratch (static device allocations — allowed)
__device__ float g_t0[MTOT * 128];   // logmap0(z_next) per (iter,row)
__device__ float g_h[MTOT * 512];    // relu(t0@W1+b1)

__device__ __forceinline__ float wsum(float v) {
#pragma unroll
    for (int o = 16; o; o >>= 1) v += __shfl_xor_sync(0xffffffffu, v, o);
    return v;
}

__device__ __forceinline__ float artanh_c(float x) {
    x = fminf(fmaxf(x, -1.0f + 1e-7f), 1.0f - 1e-7f);
    return 0.5f * logf((1.0f + x) / (1.0f - x));
}

// ---------------------------------------------------------------------------
// KA: window embedding (tan -> expmap0) + 4-step hyperbolic recurrence.
// Block = (b, group of 8 f). Warp = one (b,f) row; lane owns 4 of 128 dims.
// smem: sx[4][360][8], sw[96][128], sbias[128], sz[8][19][128], ssq[8][20]
// ---------------------------------------------------------------------------
__global__ __launch_bounds__(256, 1)
void ka_kernel(const float* __restrict__ trend, const float* __restrict__ scoar,
               const float* __restrict__ sfin,  const float* __restrict__ resid,
               const float* __restrict__ Wt, const float* __restrict__ bt,
               const float* __restrict__ Wc, const float* __restrict__ bc,
               const float* __restrict__ Wf, const float* __restrict__ bff,
               const float* __restrict__ Wr, const float* __restrict__ br,
               const float* __restrict__ alphap)
{
    extern __shared__ float sm[];
    float* sx    = sm;                    // 11520 floats
    float* sw    = sx + 11520;            // 12288 floats
    float* sbias = sw + 12288;            // 128
    float* sz    = sbias + 128;           // 8*19*128 = 19456
    float* ssq   = sz + 19456;            // 8*20 = 160

    const int tid = threadIdx.x;
    const int b   = blockIdx.x >> 4;
    const int f0  = (blockIdx.x & 15) << 3;

    // Stage inputs: last 360 time steps (segments 15..29), 8 f-columns
    {
        const float* ptrs[4] = {trend, scoar, sfin, resid};
#pragma unroll
        for (int st = 0; st < 4; ++st) {
            const float* p = ptrs[st];
            for (int idx = tid; idx < 2880; idx += 256) {
                int l = idx >> 3, f = idx & 7;
                sx[st * 2880 + idx] = p[(b * 720 + 360 + l) * 128 + f0 + f];
            }
        }
    }
    // Combined weights sw[k][d], k = stream*24+s (contiguous copies)
    for (int idx = tid; idx < 3072; idx += 256) sw[idx]        = Wt[idx];
    for (int idx = tid; idx < 3072; idx += 256) sw[3072 + idx] = Wc[idx];
    for (int idx = tid; idx < 3072; idx += 256) sw[6144 + idx] = Wf[idx];
    for (int idx = tid; idx < 3072; idx += 256) sw[9216 + idx] = Wr[idx];
    if (tid < 128) sbias[tid] = bt[tid] + bc[tid] + bff[tid] + br[tid];
    __syncthreads();

    const int w = tid >> 5, lane = tid & 31;
    const float alpha = alphap[0];
    const float4* sw4 = (const float4*)sw;
    const float4 bias4 = ((const float4*)sbias)[lane];
    float* szw  = sz + w * 19 * 128;
    float* ssqw = ssq + w * 20;

    // Build z window: z_j = expmap0(tan_j), j = 0..14
    for (int j = 0; j < 15; ++j) {
        float a0 = bias4.x, a1 = bias4.y, a2 = bias4.z, a3 = bias4.w;
#pragma unroll
        for (int st = 0; st < 4; ++st) {
            const float* sxl = sx + st * 2880 + (j * 24) * 8 + w;
#pragma unroll
            for (int s = 0; s < 24; ++s) {
                float xv = sxl[s * 8];                       // broadcast LDS
                float4 wv = sw4[(st * 24 + s) * 32 + lane];  // conflict-free LDS.128
                a0 = fmaf(xv, wv.x, a0);
                a1 = fmaf(xv, wv.y, a1);
                a2 = fmaf(xv, wv.z, a2);
                a3 = fmaf(xv, wv.w, a3);
            }
        }
        // expmap0 + project
        float n2 = wsum(a0*a0 + a1*a1 + a2*a2 + a3*a3);
        float n  = sqrtf(fmaxf(n2, 1e-12f));
        float scl = tanhf(n) / n;
        a0 *= scl; a1 *= scl; a2 *= scl; a3 *= scl;
        float yn2 = wsum(a0*a0 + a1*a1 + a2*a2 + a3*a3);
        float yn  = sqrtf(fmaxf(yn2, 1e-12f));
        if (yn > 0.99999f) {
            float ps = 0.99999f / yn;
            a0 *= ps; a1 *= ps; a2 *= ps; a3 *= ps;
            yn2 *= ps * ps;
        }
        ((float4*)(szw + j * 128))[lane] = make_float4(a0, a1, a2, a3);
        if (lane == 0) ssqw[j] = yn2;
    }
    __syncwarp();

    const float winv = 0.1f / (1.0f - powf(0.9f, 14.0f));   // 1 / sum(0.9^k, k=0..13)
    const int row = b * 128 + f0 + w;

    for (int i = 0; i < 4; ++i) {
        float av0 = 0.f, av1 = 0.f, av2 = 0.f, av3 = 0.f;
        // vel_j = logmap(z[i+j], z[i+j+1]); weighted average
        for (int j = 0; j < 14; ++j) {
            int jx = i + j;
            float4 x4 = ((const float4*)(szw + jx * 128))[lane];
            float4 y4 = ((const float4*)(szw + (jx + 1) * 128))[lane];
            float x2 = ssqw[jx], y2 = ssqw[jx + 1];
            float xy = wsum(x4.x*y4.x + x4.y*y4.y + x4.z*y4.z + x4.w*y4.w);
            // mobius_add(-x, y)
            float cA = 1.0f - 2.0f * xy + y2;        // multiplies (-x)
            float cB = 1.0f - x2;                    // multiplies y
            float iden = 1.0f / fmaxf(1.0f - 2.0f * xy + x2 * y2, 1e-6f);
            float d0 = (cB * y4.x - cA * x4.x) * iden;
            float d1 = (cB * y4.y - cA * x4.y) * iden;
            float d2 = (cB * y4.z - cA * x4.z) * iden;
            float d3 = (cB * y4.w - cA * x4.w) * iden;
            float n2 = wsum(d0*d0 + d1*d1 + d2*d2 + d3*d3);
            float n  = sqrtf(fmaxf(n2, 1e-12f));
            // (2/lam) * artanh(n) / n  with 2/lam = max(1-x2, EPS)
            float fac = fmaxf(1.0f - x2, 1e-6f) * artanh_c(n) / n;
            float wj = powf(0.9f, (float)(13 - j)) * winv;
            float t = wj * fac;
            av0 = fmaf(t, d0, av0); av1 = fmaf(t, d1, av1);
            av2 = fmaf(t, d2, av2); av3 = fmaf(t, d3, av3);
        }
        float v0 = alpha * av0, v1 = alpha * av1, v2 = alpha * av2, v3 = alpha * av3;
        // expmap(z_last, v)
        const int jl = i + 14;
        float4 xl = ((const float4*)(szw + jl * 128))[lane];
        float x2l = ssqw[jl];
        float nv2 = wsum(v0*v0 + v1*v1 + v2*v2 + v3*v3);
        float nv  = sqrtf(fmaxf(nv2, 1e-12f));
        float om  = fmaxf(1.0f - x2l, 1e-6f);
        float sscl = tanhf(nv / om) / nv;            // tanh(lam*n/2)/n
        float e0 = sscl * v0, e1 = sscl * v1, e2 = sscl * v2, e3 = sscl * v3;
        float xy = wsum(xl.x*e0 + xl.y*e1 + xl.z*e2 + xl.w*e3);
        float s2 = wsum(e0*e0 + e1*e1 + e2*e2 + e3*e3);
        float cA = 1.0f + 2.0f * xy + s2;
        float cB = 1.0f - x2l;
        float iden = 1.0f / fmaxf(1.0f + 2.0f * xy + x2l * s2, 1e-6f);
        float z0 = (cA * xl.x + cB * e0) * iden;
        float z1 = (cA * xl.y + cB * e1) * iden;
        float z2 = (cA * xl.z + cB * e2) * iden;
        float z3 = (cA * xl.w + cB * e3) * iden;
        float zn2 = wsum(z0*z0 + z1*z1 + z2*z2 + z3*z3);
        float zn  = sqrtf(fmaxf(zn2, 1e-12f));
        if (zn > 0.99999f) {
            float ps = 0.99999f / zn;
            z0 *= ps; z1 *= ps; z2 *= ps; z3 *= ps;
            zn2 *= ps * ps;
        }
        ((float4*)(szw + (i + 15) * 128))[lane] = make_float4(z0, z1, z2, z3);
        if (lane == 0) ssqw[i + 15] = zn2;
        __syncwarp();
        // t0 = logmap0(z_next)
        float tn = sqrtf(fmaxf(zn2, 1e-12f));
        float tf = artanh_c(tn) / tn;
        ((float4*)(g_t0 + (i * NROW + row) * 128))[lane] =
            make_float4(tf * z0, tf * z1, tf * z2, tf * z3);
    }
}

// ---------------------------------------------------------------------------
// KB: h = relu(t0 @ W1 + b1).  M=65536, K=128, N=512.
// Block: 64-row x 128-col tile, 256 threads, thread micro-tile 8x4.
// ---------------------------------------------------------------------------
__global__ __launch_bounds__(256, 2)
void kb_kernel(const float* __restrict__ W1, const float* __restrict__ b1)
{
    extern __shared__ float sm[];
    float* sA = sm;            // 64*128
    float* sB = sm + 64 * 128; // 128*128
    const int tid = threadIdx.x;
    const int mbase = blockIdx.x * 64;
    const int nbase = blockIdx.y * 128;

    for (int idx = tid; idx < 64 * 128; idx += 256)
        sA[idx] = g_t0[(mbase + (idx >> 7)) * 128 + (idx & 127)];
    for (int idx = tid; idx < 128 * 128; idx += 256)
        sB[idx] = W1[(idx >> 7) * 512 + nbase + (idx & 127)];
    __syncthreads();

    const int tx = tid & 31, ty = tid >> 5;
    const int r0 = ty * 8, c0 = tx * 4;
    float4 acc[8];
#pragma unroll
    for (int r = 0; r < 8; ++r) acc[r] = make_float4(0.f, 0.f, 0.f, 0.f);

    const float4* sB4 = (const float4*)sB;
#pragma unroll 8
    for (int k = 0; k < 128; ++k) {
        float4 bv = sB4[k * 32 + tx];
#pragma unroll
        for (int r = 0; r < 8; ++r) {
            float a = sA[(r0 + r) * 128 + k];   // broadcast within warp
            acc[r].x = fmaf(a, bv.x, acc[r].x);
            acc[r].y = fmaf(a, bv.y, acc[r].y);
            acc[r].z = fmaf(a, bv.z, acc[r].z);
            acc[r].w = fmaf(a, bv.w, acc[r].w);
        }
    }
    float4 bb = ((const float4*)(b1 + nbase))[tx];
#pragma unroll
    for (int r = 0; r < 8; ++r) {
        float4 h;
        h.x = fmaxf(acc[r].x + bb.x, 0.f);
        h.y = fmaxf(acc[r].y + bb.y, 0.f);
        h.z = fmaxf(acc[r].z + bb.z, 0.f);
        h.w = fmaxf(acc[r].w + bb.w, 0.f);
        ((float4*)(g_h + (mbase + r0 + r) * 512 + nbase + c0))[0] = h;
    }
}

// ---------------------------------------------------------------------------
// KC: pred = h @ W2 + b2, written directly in (b, t, f) output layout.
// Block = (iter i, batch b): 128 f-rows x 24 outputs, K=512 in 4 chunks.
// Thread: f = tid&127, s-half = tid>>7 (12 outputs each).
// ---------------------------------------------------------------------------
__global__ __launch_bounds__(256, 1)
void kc_kernel(float* __restrict__ out, const float* __restrict__ W2,
               const float* __restrict__ b2)
{
    extern __shared__ float sm[];
    float* sW2 = sm;           // 512*24 = 12288
    float* sH  = sm + 12288;   // 128*129 = 16512 (padded vs bank conflicts)
    const int tid = threadIdx.x;
    const int i = blockIdx.x;   // iter 0..3
    const int b = blockIdx.y;   // batch 0..127

    for (int idx = tid; idx < 512 * 24; idx += 256) sW2[idx] = W2[idx];

    const int f  = tid & 127;
    const int sh = tid >> 7;
    float acc[12];
#pragma unroll
    for (int j = 0; j < 12; ++j) acc[j] = 0.f;

    const int rowbase = (i * NROW + b * 128) * 512;
    for (int kc = 0; kc < 4; ++kc) {
        __syncthreads();
        for (int idx = tid; idx < 128 * 128; idx += 256) {
            int ff = idx >> 7, k = idx & 127;
            sH[ff * 129 + k] = g_h[rowbase + ff * 512 + kc * 128 + k];
        }
        __syncthreads();
#pragma unroll 4
        for (int k = 0; k < 128; ++k) {
            float hv = sH[f * 129 + k];
            const float* wrow = sW2 + (kc * 128 + k) * 24 + sh * 12;
#pragma unroll
            for (int j = 0; j < 12; ++j) acc[j] = fmaf(hv, wrow[j], acc[j]);
        }
    }
#pragma unroll
    for (int j = 0; j < 12; ++j) {
        int s = sh * 12 + j;
        out[(b * 96 + i * 24 + s) * 128 + f] = acc[j] + b2[s];
    }
}

// ---------------------------------------------------------------------------
extern "C" void kernel_launch(void* const* d_in, const int* in_sizes, int n_in,
                              void* d_out, int out_size)
{
    const float* trend = (const float*)d_in[0];
    const float* scoar = (const float*)d_in[1];
    const float* sfin  = (const float*)d_in[2];
    const float* resid = (const float*)d_in[3];
    const float* Wt = (const float*)d_in[4];
    const float* bt = (const float*)d_in[5];
    const float* Wc = (const float*)d_in[6];
    const float* bc = (const float*)d_in[7];
    const float* Wf = (const float*)d_in[8];
    const float* bf = (const float*)d_in[9];
    const float* Wr = (const float*)d_in[10];
    const float* br = (const float*)d_in[11];
    const float* alpha = (const float*)d_in[12];
    const float* W1 = (const float*)d_in[13];
    const float* b1 = (const float*)d_in[14];
    const float* W2 = (const float*)d_in[15];
    const float* b2 = (const float*)d_in[16];

    // Attribute calls execute immediately; first (non-captured) correctness
    // call sets them persistently, so repeats during capture are harmless.
    cudaFuncSetAttribute(ka_kernel, cudaFuncAttributeMaxDynamicSharedMemorySize, 174208);
    cudaFuncSetAttribute(kb_kernel, cudaFuncAttributeMaxDynamicSharedMemorySize, 98304);
    cudaFuncSetAttribute(kc_kernel, cudaFuncAttributeMaxDynamicSharedMemorySize, 115200);

    ka_kernel<<<2048, 256, 174208>>>(trend, scoar, sfin, resid,
                                     Wt, bt, Wc, bc, Wf, bf, Wr, br, alpha);
    kb_kernel<<<dim3(1024, 4), 256, 98304>>>(W1, b1);
    kc_kernel<<<dim3(4, 128), 256, 115200>>>((float*)d_out, W2, b2);
}

// round 8
// speedup vs baseline: 2.6360x; 2.6333x over previous
#include <cuda_runtime.h>
#include <math.h>

#define NROW 16384          // B*F rows
#define MTOT 65536          // NPRED * NROW

// Scratch (static device arrays — allocation-free)
__device__ float g_z[NROW * 15 * 128];   // window embeddings z_0..z_14 per row
__device__ float g_zn2[NROW * 15];       // squared norms of z
__device__ float g_t0[MTOT * 128];       // logmap0(z_next) per (iter,row)

// ---------------------------------------------------------------- helpers
__device__ __forceinline__ float wsum(float v) {
#pragma unroll
    for (int o = 16; o; o >>= 1) v += __shfl_xor_sync(0xffffffffu, v, o);
    return v;
}
__device__ __forceinline__ float artanh_c(float x) {
    x = fminf(fmaxf(x, -1.0f + 1e-7f), 1.0f - 1e-7f);
    return 0.5f * logf((1.0f + x) / (1.0f - x));
}
typedef unsigned long long ull;
__device__ __forceinline__ void fma2(ull& c, ull a, ull b) {
    asm("fma.rn.f32x2 %0, %1, %2, %0;" : "+l"(c) : "l"(a), "l"(b));
}
__device__ __forceinline__ ull splat2(float x) {
    ull r; asm("mov.b64 %0, {%1, %1};" : "=l"(r) : "f"(x)); return r;
}
__device__ __forceinline__ ull pack2(float lo, float hi) {
    ull r; asm("mov.b64 %0, {%1, %2};" : "=l"(r) : "f"(lo), "f"(hi)); return r;
}
__device__ __forceinline__ void unpack2(ull v, float& lo, float& hi) {
    asm("mov.b64 {%0, %1}, %2;" : "=f"(lo), "=f"(hi) : "l"(v));
}

// logmap(x, y) -> velocity vector (lane holds 4 of 128 dims)
__device__ __forceinline__ void logmap_v(float4 x4, float x2, float4 y4, float y2,
                                         float& v0, float& v1, float& v2, float& v3)
{
    float xy = wsum(x4.x*y4.x + x4.y*y4.y + x4.z*y4.z + x4.w*y4.w);
    float cA = 1.0f - 2.0f*xy + y2;
    float cB = 1.0f - x2;
    float iden = 1.0f / fmaxf(1.0f - 2.0f*xy + x2*y2, 1e-6f);
    float d0 = (cB*y4.x - cA*x4.x)*iden;
    float d1 = (cB*y4.y - cA*x4.y)*iden;
    float d2 = (cB*y4.z - cA*x4.z)*iden;
    float d3 = (cB*y4.w - cA*x4.w)*iden;
    float n2 = wsum(d0*d0 + d1*d1 + d2*d2 + d3*d3);
    float n  = sqrtf(fmaxf(n2, 1e-12f));
    float fac = fmaxf(cB, 1e-6f) * artanh_c(n) / n;
    v0 = fac*d0; v1 = fac*d1; v2 = fac*d2; v3 = fac*d3;
}

// ---------------------------------------------------------------------------
// KA1: embedding GEMM + expmap0.  Block = (b, segment j of window).
// Computes z[(b,f), j, :] for all 128 f.  Warp = 16 f rows, lane = 4 dims.
// smem: sA[96][128] (x, f-contig) + sW[96][128] + sbias[128]  = 96.5 KB
// ---------------------------------------------------------------------------
__global__ __launch_bounds__(256, 2)
void ka1_kernel(const float* __restrict__ trend, const float* __restrict__ scoar,
                const float* __restrict__ sfin,  const float* __restrict__ resid,
                const float* __restrict__ Wt, const float* __restrict__ bt,
                const float* __restrict__ Wc, const float* __restrict__ bc,
                const float* __restrict__ Wf, const float* __restrict__ bff,
                const float* __restrict__ Wr, const float* __restrict__ br)
{
    extern __shared__ float sm[];
    float* sA    = sm;            // 12288
    float* sW    = sA + 12288;    // 12288
    float* sbias = sW + 12288;    // 128

    const int tid = threadIdx.x;
    const int b = blockIdx.x / 15;
    const int j = blockIdx.x - b * 15;
    const int lbase = b * 720 + 360 + j * 24;

    {
        const float* ptrs[4] = {trend, scoar, sfin, resid};
        const float* wptr[4] = {Wt, Wc, Wf, Wr};
#pragma unroll
        for (int st = 0; st < 4; ++st) {
            const float* p = ptrs[st] + lbase * 128;
            for (int idx = tid; idx < 3072; idx += 256) sA[st * 3072 + idx] = p[idx];
            const float* wp = wptr[st];
            for (int idx = tid; idx < 3072; idx += 256) sW[st * 3072 + idx] = wp[idx];
        }
    }
    if (tid < 128) sbias[tid] = bt[tid] + bc[tid] + bff[tid] + br[tid];
    __syncthreads();

    const int w = tid >> 5, lane = tid & 31;
    const int fb = w * 16;

    ull bias01 = pack2(sbias[lane*4],   sbias[lane*4+1]);
    ull bias23 = pack2(sbias[lane*4+2], sbias[lane*4+3]);
    ull acc[16][2];
#pragma unroll
    for (int r = 0; r < 16; ++r) { acc[r][0] = bias01; acc[r][1] = bias23; }

    const float4* sW4 = (const float4*)sW;
#pragma unroll 4
    for (int k = 0; k < 96; ++k) {
        float4 wv = sW4[k * 32 + lane];          // per-lane weights (4 dims)
        ull w01 = pack2(wv.x, wv.y);
        ull w23 = pack2(wv.z, wv.w);
        const float4* xr = (const float4*)(sA + k * 128 + fb);
#pragma unroll
        for (int g = 0; g < 4; ++g) {
            float4 x4 = xr[g];                   // broadcast: x for 4 f rows
            ull s0 = splat2(x4.x), s1 = splat2(x4.y), s2 = splat2(x4.z), s3 = splat2(x4.w);
            fma2(acc[g*4+0][0], s0, w01); fma2(acc[g*4+0][1], s0, w23);
            fma2(acc[g*4+1][0], s1, w01); fma2(acc[g*4+1][1], s1, w23);
            fma2(acc[g*4+2][0], s2, w01); fma2(acc[g*4+2][1], s2, w23);
            fma2(acc[g*4+3][0], s3, w01); fma2(acc[g*4+3][1], s3, w23);
        }
    }

    const int rowb = b * 128 + fb;
#pragma unroll
    for (int r = 0; r < 16; ++r) {
        float a0, a1, a2, a3;
        unpack2(acc[r][0], a0, a1);
        unpack2(acc[r][1], a2, a3);
        // expmap0 + project (same numerics as the passing kernel)
        float n2 = wsum(a0*a0 + a1*a1 + a2*a2 + a3*a3);
        float n  = sqrtf(fmaxf(n2, 1e-12f));
        float scl = tanhf(n) / n;
        a0 *= scl; a1 *= scl; a2 *= scl; a3 *= scl;
        float yn2 = wsum(a0*a0 + a1*a1 + a2*a2 + a3*a3);
        float yn  = sqrtf(fmaxf(yn2, 1e-12f));
        if (yn > 0.99999f) {
            float ps = 0.99999f / yn;
            a0 *= ps; a1 *= ps; a2 *= ps; a3 *= ps;
            yn2 *= ps * ps;
        }
        int row = rowb + r;
        ((float4*)(g_z + (row * 15 + j) * 128))[lane] = make_float4(a0, a1, a2, a3);
        if (lane == 0) g_zn2[row * 15 + j] = yn2;
    }
}

// ---------------------------------------------------------------------------
// KA2: 4-step recurrence with sliding weighted velocity average.
// Warp = one (b,f) row; lane = 4 dims. Zero smem -> high occupancy.
// avg_{i+1} = 0.9*(avg_i - w0*vel_i) + w13*vel_new   (w[j-1] = 0.9*w[j])
// ---------------------------------------------------------------------------
__global__ __launch_bounds__(256)
void ka2_kernel(const float* __restrict__ alphap)
{
    const int w = threadIdx.x >> 5, lane = threadIdx.x & 31;
    const int row = blockIdx.x * 8 + w;
    const float alpha = alphap[0];

    // weights: w[j] = 0.9^(13-j)/S
    float S = 0.0f, p = 1.0f;
#pragma unroll
    for (int e = 0; e < 14; ++e) { S += p; p *= 0.9f; }
    const float w13 = 1.0f / S;
    float w0 = w13;
#pragma unroll
    for (int e = 0; e < 13; ++e) w0 *= 0.9f;
    const float inv09 = 1.0f / 0.9f;

    const float* zp = g_z   + row * 15 * 128;
    const float* np = g_zn2 + row * 15;

    float4 x4 = ((const float4*)zp)[lane];
    float  x2 = np[0];
    float av0 = 0.f, av1 = 0.f, av2 = 0.f, av3 = 0.f;
    float vc[3][4];
    float wcur = w0;

    // first 3 velocities cached (they are dropped in later iterations)
#pragma unroll
    for (int jj = 0; jj < 3; ++jj) {
        float4 y4 = ((const float4*)(zp + (jj + 1) * 128))[lane];
        float  y2 = np[jj + 1];
        float v0, v1, v2, v3;
        logmap_v(x4, x2, y4, y2, v0, v1, v2, v3);
        vc[jj][0] = v0; vc[jj][1] = v1; vc[jj][2] = v2; vc[jj][3] = v3;
        av0 = fmaf(wcur, v0, av0); av1 = fmaf(wcur, v1, av1);
        av2 = fmaf(wcur, v2, av2); av3 = fmaf(wcur, v3, av3);
        wcur *= inv09;
        x4 = y4; x2 = y2;
    }
    for (int jj = 3; jj < 14; ++jj) {
        float4 y4 = ((const float4*)(zp + (jj + 1) * 128))[lane];
        float  y2 = np[jj + 1];
        float v0, v1, v2, v3;
        logmap_v(x4, x2, y4, y2, v0, v1, v2, v3);
        av0 = fmaf(wcur, v0, av0); av1 = fmaf(wcur, v1, av1);
        av2 = fmaf(wcur, v2, av2); av3 = fmaf(wcur, v3, av3);
        wcur *= inv09;
        x4 = y4; x2 = y2;
    }
    // x4/x2 now hold z_14 (= z_last)

#pragma unroll
    for (int i = 0; i < 4; ++i) {
        float v0 = alpha * av0, v1 = alpha * av1, v2 = alpha * av2, v3 = alpha * av3;
        // expmap(z_last, v)
        float nv2 = wsum(v0*v0 + v1*v1 + v2*v2 + v3*v3);
        float nv  = sqrtf(fmaxf(nv2, 1e-12f));
        float om  = fmaxf(1.0f - x2, 1e-6f);
        float sscl = tanhf(nv / om) / nv;
        float e0 = sscl*v0, e1 = sscl*v1, e2 = sscl*v2, e3 = sscl*v3;
        float xy = wsum(x4.x*e0 + x4.y*e1 + x4.z*e2 + x4.w*e3);
        float s2 = wsum(e0*e0 + e1*e1 + e2*e2 + e3*e3);
        float cA = 1.0f + 2.0f*xy + s2;
        float cB = 1.0f - x2;
        float iden = 1.0f / fmaxf(1.0f + 2.0f*xy + x2*s2, 1e-6f);
        float z0 = (cA*x4.x + cB*e0)*iden;
        float z1 = (cA*x4.y + cB*e1)*iden;
        float z2 = (cA*x4.z + cB*e2)*iden;
        float z3 = (cA*x4.w + cB*e3)*iden;
        float zn2 = wsum(z0*z0 + z1*z1 + z2*z2 + z3*z3);
        float zn  = sqrtf(fmaxf(zn2, 1e-12f));
        if (zn > 0.99999f) {
            float ps = 0.99999f / zn;
            z0 *= ps; z1 *= ps; z2 *= ps; z3 *= ps;
            zn2 *= ps * ps;
        }
        // t0 = logmap0(z_next)
        float tn = sqrtf(fmaxf(zn2, 1e-12f));
        float tf = artanh_c(tn) / tn;
        ((float4*)(g_t0 + (i * NROW + row) * 128))[lane] =
            make_float4(tf*z0, tf*z1, tf*z2, tf*z3);

        if (i < 3) {
            float4 zn4 = make_float4(z0, z1, z2, z3);
            float nv0, nv1, nv2b, nv3;
            logmap_v(x4, x2, zn4, zn2, nv0, nv1, nv2b, nv3);   // vel_new
            av0 = fmaf(0.9f, av0 - w0 * vc[i][0], w13 * nv0);
            av1 = fmaf(0.9f, av1 - w0 * vc[i][1], w13 * nv1);
            av2 = fmaf(0.9f, av2 - w0 * vc[i][2], w13 * nv2b);
            av3 = fmaf(0.9f, av3 - w0 * vc[i][3], w13 * nv3);
        }
        x4 = make_float4(z0, z1, z2, z3); x2 = zn2;
    }
}

// ---------------------------------------------------------------------------
// KBC: fused MLP.  Block = 64 rows of one (iter).  grid = 4*256 = 1024.
// Per N-chunk (64 cols of W1): h = relu(t0@W1c + b1c) kept in smem, then
// out += h @ W2c, accumulated in registers.  smem ~88 KB -> 2 blocks/SM.
// ---------------------------------------------------------------------------
__global__ __launch_bounds__(256, 2)
void kbc_kernel(float* __restrict__ out, const float* __restrict__ W1,
                const float* __restrict__ b1, const float* __restrict__ W2,
                const float* __restrict__ b2)
{
    extern __shared__ float sm[];
    float* sT  = sm;                 // [128 k][68]  (rows, padded)
    float* sW1 = sT + 128 * 68;      // [128 k][64 c]
    float* sH  = sW1 + 128 * 64;     // [64 r][65 k2]
    float* sW2 = sH + 64 * 65;       // [64 k2][24 s]

    const int tid = threadIdx.x;
    const int i  = blockIdx.x >> 8;          // iter 0..3
    const int rb = blockIdx.x & 255;
    const int rowbase = rb * 64;

    // stage t0 tile transposed: sT[k][r]
    {
        const float* src = g_t0 + (i * NROW + rowbase) * 128;
        for (int idx = tid; idx < 64 * 128; idx += 256) {
            int r = idx >> 7, k = idx & 127;
            sT[k * 68 + r] = src[idx];
        }
    }

    const int tx = tid & 15, ty = tid >> 4;
    const int c0 = tx * 4, r0 = ty * 4;
    const int fl = tid & 63, sq = tid >> 6;   // GEMM2 mapping: 64 f x 4 groups of 6 s

    ull acc6[3] = {0ull, 0ull, 0ull};

    for (int nc = 0; nc < 8; ++nc) {
        __syncthreads();   // previous chunk fully consumed
        for (int idx = tid; idx < 128 * 64; idx += 256) {
            int k = idx >> 6, c = idx & 63;
            sW1[idx] = W1[k * 512 + nc * 64 + c];
        }
        {
            const float* w2p = W2 + nc * 64 * 24;
            for (int idx = tid; idx < 64 * 24; idx += 256) sW2[idx] = w2p[idx];
        }
        __syncthreads();

        // GEMM1: h[r0..r0+3][c0..c0+3] = t0 @ W1c + b1, relu, into sH
        float4 bb = *(const float4*)&b1[nc * 64 + c0];
        ull b01 = pack2(bb.x, bb.y), b23 = pack2(bb.z, bb.w);
        ull hacc[4][2];
#pragma unroll
        for (int r = 0; r < 4; ++r) { hacc[r][0] = b01; hacc[r][1] = b23; }
#pragma unroll 4
        for (int k = 0; k < 128; ++k) {
            float4 rv = *(const float4*)&sT[k * 68 + r0];    // broadcast (2 addrs/warp)
            float4 wv = *(const float4*)&sW1[k * 64 + c0];   // per-lane
            ull w01 = pack2(wv.x, wv.y), w23 = pack2(wv.z, wv.w);
            ull s0 = splat2(rv.x), s1 = splat2(rv.y), s2 = splat2(rv.z), s3 = splat2(rv.w);
            fma2(hacc[0][0], s0, w01); fma2(hacc[0][1], s0, w23);
            fma2(hacc[1][0], s1, w01); fma2(hacc[1][1], s1, w23);
            fma2(hacc[2][0], s2, w01); fma2(hacc[2][1], s2, w23);
            fma2(hacc[3][0], s3, w01); fma2(hacc[3][1], s3, w23);
        }
#pragma unroll
        for (int r = 0; r < 4; ++r) {
            float h0, h1, h2, h3;
            unpack2(hacc[r][0], h0, h1);
            unpack2(hacc[r][1], h2, h3);
            float* dst = sH + (r0 + r) * 65 + c0;
            dst[0] = fmaxf(h0, 0.f); dst[1] = fmaxf(h1, 0.f);
            dst[2] = fmaxf(h2, 0.f); dst[3] = fmaxf(h3, 0.f);
        }
        __syncthreads();

        // GEMM2: out[fl][sq*6..+5] += h[fl][:] @ W2c
#pragma unroll 2
        for (int k2 = 0; k2 < 64; ++k2) {
            float hv = sH[fl * 65 + k2];                      // conflict-free
            ull hs = splat2(hv);
            const float* w2r = sW2 + k2 * 24 + sq * 6;        // broadcast per warp
            float2 wa = *(const float2*)w2r;
            float2 wb = *(const float2*)(w2r + 2);
            float2 wc = *(const float2*)(w2r + 4);
            fma2(acc6[0], hs, pack2(wa.x, wa.y));
            fma2(acc6[1], hs, pack2(wb.x, wb.y));
            fma2(acc6[2], hs, pack2(wc.x, wc.y));
        }
    }

    // write predictions in output layout out[(b*96 + i*24 + s)*128 + f]
    const int row_g = rowbase + fl;
    const int b  = row_g >> 7;
    const int f  = row_g & 127;
    float o[6];
    unpack2(acc6[0], o[0], o[1]);
    unpack2(acc6[1], o[2], o[3]);
    unpack2(acc6[2], o[4], o[5]);
#pragma unroll
    for (int jj = 0; jj < 6; ++jj) {
        int s = sq * 6 + jj;
        out[(b * 96 + i * 24 + s) * 128 + f] = o[jj] + b2[s];
    }
}

// ---------------------------------------------------------------------------
extern "C" void kernel_launch(void* const* d_in, const int* in_sizes, int n_in,
                              void* d_out, int out_size)
{
    const float* trend = (const float*)d_in[0];
    const float* scoar = (const float*)d_in[1];
    const float* sfin  = (const float*)d_in[2];
    const float* resid = (const float*)d_in[3];
    const float* Wt = (const float*)d_in[4];
    const float* bt = (const float*)d_in[5];
    const float* Wc = (const float*)d_in[6];
    const float* bc = (const float*)d_in[7];
    const float* Wf = (const float*)d_in[8];
    const float* bf = (const float*)d_in[9];
    const float* Wr = (const float*)d_in[10];
    const float* br = (const float*)d_in[11];
    const float* alpha = (const float*)d_in[12];
    const float* W1 = (const float*)d_in[13];
    const float* b1 = (const float*)d_in[14];
    const float* W2 = (const float*)d_in[15];
    const float* b2 = (const float*)d_in[16];

    cudaFuncSetAttribute(ka1_kernel, cudaFuncAttributeMaxDynamicSharedMemorySize, 98816);
    cudaFuncSetAttribute(kbc_kernel, cudaFuncAttributeMaxDynamicSharedMemorySize, 90368);

    ka1_kernel<<<1920, 256, 98816>>>(trend, scoar, sfin, resid,
                                     Wt, bt, Wc, bc, Wf, bf, Wr, br);
    ka2_kernel<<<2048, 256>>>(alpha);
    kbc_kernel<<<1024, 256, 90368>>>((float*)d_out, W1, b1, W2, b2);
}

// round 9
// speedup vs baseline: 3.1179x; 1.1828x over previous
#include <cuda_runtime.h>
#include <math.h>

#define NROW 16384          // B*F rows
#define MTOT 65536          // NPRED * NROW

// Scratch (static device arrays — allocation-free)
__device__ float g_z[NROW * 15 * 128];   // window embeddings z_0..z_14 per row
__device__ float g_zn2[NROW * 15];       // squared norms of z
__device__ float g_t0[MTOT * 128];       // logmap0(z_next) per (iter,row)

// ---------------------------------------------------------------- helpers
__device__ __forceinline__ float wsum(float v) {
#pragma unroll
    for (int o = 16; o; o >>= 1) v += __shfl_xor_sync(0xffffffffu, v, o);
    return v;
}
__device__ __forceinline__ float artanh_c(float x) {
    x = fminf(fmaxf(x, -1.0f + 1e-7f), 1.0f - 1e-7f);
    return 0.5f * logf((1.0f + x) / (1.0f - x));
}
typedef unsigned long long ull;
__device__ __forceinline__ void fma2(ull& c, ull a, ull b) {
    asm("fma.rn.f32x2 %0, %1, %2, %0;" : "+l"(c) : "l"(a), "l"(b));
}
__device__ __forceinline__ ull splat2(float x) {
    ull r; asm("mov.b64 %0, {%1, %1};" : "=l"(r) : "f"(x)); return r;
}
__device__ __forceinline__ void unpack2(ull v, float& lo, float& hi) {
    asm("mov.b64 {%0, %1}, %2;" : "=f"(lo), "=f"(hi) : "l"(v));
}
// 16B shared load delivering two packed f32 pairs (no movs)
__device__ __forceinline__ void lds2u(ull& a, ull& b, const float* p) {
    unsigned sa = (unsigned)__cvta_generic_to_shared(p);
    asm("ld.shared.v2.b64 {%0,%1}, [%2];" : "=l"(a), "=l"(b) : "r"(sa));
}

// logmap(x, y) -> velocity vector (lane holds 4 of 128 dims)
__device__ __forceinline__ void logmap_v(float4 x4, float x2, float4 y4, float y2,
                                         float& v0, float& v1, float& v2, float& v3)
{
    float xy = wsum(x4.x*y4.x + x4.y*y4.y + x4.z*y4.z + x4.w*y4.w);
    float cA = 1.0f - 2.0f*xy + y2;
    float cB = 1.0f - x2;
    float iden = 1.0f / fmaxf(1.0f - 2.0f*xy + x2*y2, 1e-6f);
    float d0 = (cB*y4.x - cA*x4.x)*iden;
    float d1 = (cB*y4.y - cA*x4.y)*iden;
    float d2 = (cB*y4.z - cA*x4.z)*iden;
    float d3 = (cB*y4.w - cA*x4.w)*iden;
    float n2 = wsum(d0*d0 + d1*d1 + d2*d2 + d3*d3);
    float n  = sqrtf(fmaxf(n2, 1e-12f));
    float fac = fmaxf(cB, 1e-6f) * artanh_c(n) / n;
    v0 = fac*d0; v1 = fac*d1; v2 = fac*d2; v3 = fac*d3;
}

// ---------------------------------------------------------------------------
// KA1: embedding GEMM + expmap0.  Block = (b, segment j of window).
// Warp = 16 f rows (8 packed f-pairs), lane = 4 dims.
// a-operands are direct b64 pairs from f-contiguous sA (no splats);
// only the 4 per-lane weight splats remain.
// ---------------------------------------------------------------------------
__global__ __launch_bounds__(256, 2)
void ka1_kernel(const float* __restrict__ trend, const float* __restrict__ scoar,
                const float* __restrict__ sfin,  const float* __restrict__ resid,
                const float* __restrict__ Wt, const float* __restrict__ bt,
                const float* __restrict__ Wc, const float* __restrict__ bc,
                const float* __restrict__ Wf, const float* __restrict__ bff,
                const float* __restrict__ Wr, const float* __restrict__ br)
{
    extern __shared__ float sm[];
    float* sA    = sm;            // [96 k][128 f]
    float* sW    = sA + 12288;    // [96 k][128 d]
    float* sbias = sW + 12288;    // 128

    const int tid = threadIdx.x;
    const int b = blockIdx.x / 15;
    const int j = blockIdx.x - b * 15;
    const int lbase = b * 720 + 360 + j * 24;

    {
        const float* ptrs[4] = {trend, scoar, sfin, resid};
        const float* wptr[4] = {Wt, Wc, Wf, Wr};
#pragma unroll
        for (int st = 0; st < 4; ++st) {
            const float* p = ptrs[st] + lbase * 128;
            for (int idx = tid; idx < 3072; idx += 256) sA[st * 3072 + idx] = p[idx];
            const float* wp = wptr[st];
            for (int idx = tid; idx < 3072; idx += 256) sW[st * 3072 + idx] = wp[idx];
        }
    }
    if (tid < 128) sbias[tid] = bt[tid] + bc[tid] + bff[tid] + br[tid];
    __syncthreads();

    const int w = tid >> 5, lane = tid & 31;
    const int fb = w * 16;

    const float4 bias4 = ((const float4*)sbias)[lane];
    ull bini[4] = { splat2(bias4.x), splat2(bias4.y), splat2(bias4.z), splat2(bias4.w) };
    // acc[fpair][dim] : lo = f even, hi = f odd
    ull acc[8][4];
#pragma unroll
    for (int p = 0; p < 8; ++p)
#pragma unroll
        for (int d = 0; d < 4; ++d) acc[p][d] = bini[d];

    const float4* sW4 = (const float4*)sW;
#pragma unroll 2
    for (int k = 0; k < 96; ++k) {
        float4 wv = sW4[k * 32 + lane];           // per-lane weights, 4 dims
        ull wd0 = splat2(wv.x), wd1 = splat2(wv.y), wd2 = splat2(wv.z), wd3 = splat2(wv.w);
        const float* ab = sA + k * 128 + fb;      // f-contiguous (broadcast)
        ull a0, a1, a2, a3, a4, a5, a6, a7;
        lds2u(a0, a1, ab);
        lds2u(a2, a3, ab + 4);
        lds2u(a4, a5, ab + 8);
        lds2u(a6, a7, ab + 12);
        fma2(acc[0][0], a0, wd0); fma2(acc[0][1], a0, wd1); fma2(acc[0][2], a0, wd2); fma2(acc[0][3], a0, wd3);
        fma2(acc[1][0], a1, wd0); fma2(acc[1][1], a1, wd1); fma2(acc[1][2], a1, wd2); fma2(acc[1][3], a1, wd3);
        fma2(acc[2][0], a2, wd0); fma2(acc[2][1], a2, wd1); fma2(acc[2][2], a2, wd2); fma2(acc[2][3], a2, wd3);
        fma2(acc[3][0], a3, wd0); fma2(acc[3][1], a3, wd1); fma2(acc[3][2], a3, wd2); fma2(acc[3][3], a3, wd3);
        fma2(acc[4][0], a4, wd0); fma2(acc[4][1], a4, wd1); fma2(acc[4][2], a4, wd2); fma2(acc[4][3], a4, wd3);
        fma2(acc[5][0], a5, wd0); fma2(acc[5][1], a5, wd1); fma2(acc[5][2], a5, wd2); fma2(acc[5][3], a5, wd3);
        fma2(acc[6][0], a6, wd0); fma2(acc[6][1], a6, wd1); fma2(acc[6][2], a6, wd2); fma2(acc[6][3], a6, wd3);
        fma2(acc[7][0], a7, wd0); fma2(acc[7][1], a7, wd1); fma2(acc[7][2], a7, wd2); fma2(acc[7][3], a7, wd3);
    }

    const int rowb = b * 128 + fb;
#pragma unroll
    for (int p = 0; p < 8; ++p) {
        float lo[4], hi[4];
#pragma unroll
        for (int d = 0; d < 4; ++d) unpack2(acc[p][d], lo[d], hi[d]);
#pragma unroll
        for (int e = 0; e < 2; ++e) {
            float a0 = e ? hi[0] : lo[0];
            float a1 = e ? hi[1] : lo[1];
            float a2 = e ? hi[2] : lo[2];
            float a3 = e ? hi[3] : lo[3];
            // expmap0 + project (numerics identical to passing kernel)
            float n2 = wsum(a0*a0 + a1*a1 + a2*a2 + a3*a3);
            float n  = sqrtf(fmaxf(n2, 1e-12f));
            float scl = tanhf(n) / n;
            a0 *= scl; a1 *= scl; a2 *= scl; a3 *= scl;
            float yn2 = wsum(a0*a0 + a1*a1 + a2*a2 + a3*a3);
            float yn  = sqrtf(fmaxf(yn2, 1e-12f));
            if (yn > 0.99999f) {
                float ps = 0.99999f / yn;
                a0 *= ps; a1 *= ps; a2 *= ps; a3 *= ps;
                yn2 *= ps * ps;
            }
            int row = rowb + 2 * p + e;
            ((float4*)(g_z + (row * 15 + j) * 128))[lane] = make_float4(a0, a1, a2, a3);
            if (lane == 0) g_zn2[row * 15 + j] = yn2;
        }
    }
}

// ---------------------------------------------------------------------------
// KA2: 4-step recurrence with sliding weighted velocity average.
// Warp = one (b,f) row; lane = 4 dims. Zero smem -> high occupancy.
// ---------------------------------------------------------------------------
__global__ __launch_bounds__(256)
void ka2_kernel(const float* __restrict__ alphap)
{
    const int w = threadIdx.x >> 5, lane = threadIdx.x & 31;
    const int row = blockIdx.x * 8 + w;
    const float alpha = alphap[0];

    float S = 0.0f, p = 1.0f;
#pragma unroll
    for (int e = 0; e < 14; ++e) { S += p; p *= 0.9f; }
    const float w13 = 1.0f / S;
    float w0 = w13;
#pragma unroll
    for (int e = 0; e < 13; ++e) w0 *= 0.9f;
    const float inv09 = 1.0f / 0.9f;

    const float* zp = g_z   + row * 15 * 128;
    const float* np = g_zn2 + row * 15;

    float4 x4 = ((const float4*)zp)[lane];
    float  x2 = np[0];
    float av0 = 0.f, av1 = 0.f, av2 = 0.f, av3 = 0.f;
    float vc[3][4];
    float wcur = w0;

#pragma unroll
    for (int jj = 0; jj < 3; ++jj) {
        float4 y4 = ((const float4*)(zp + (jj + 1) * 128))[lane];
        float  y2 = np[jj + 1];
        float v0, v1, v2, v3;
        logmap_v(x4, x2, y4, y2, v0, v1, v2, v3);
        vc[jj][0] = v0; vc[jj][1] = v1; vc[jj][2] = v2; vc[jj][3] = v3;
        av0 = fmaf(wcur, v0, av0); av1 = fmaf(wcur, v1, av1);
        av2 = fmaf(wcur, v2, av2); av3 = fmaf(wcur, v3, av3);
        wcur *= inv09;
        x4 = y4; x2 = y2;
    }
    for (int jj = 3; jj < 14; ++jj) {
        float4 y4 = ((const float4*)(zp + (jj + 1) * 128))[lane];
        float  y2 = np[jj + 1];
        float v0, v1, v2, v3;
        logmap_v(x4, x2, y4, y2, v0, v1, v2, v3);
        av0 = fmaf(wcur, v0, av0); av1 = fmaf(wcur, v1, av1);
        av2 = fmaf(wcur, v2, av2); av3 = fmaf(wcur, v3, av3);
        wcur *= inv09;
        x4 = y4; x2 = y2;
    }

#pragma unroll
    for (int i = 0; i < 4; ++i) {
        float v0 = alpha * av0, v1 = alpha * av1, v2 = alpha * av2, v3 = alpha * av3;
        float nv2 = wsum(v0*v0 + v1*v1 + v2*v2 + v3*v3);
        float nv  = sqrtf(fmaxf(nv2, 1e-12f));
        float om  = fmaxf(1.0f - x2, 1e-6f);
        float sscl = tanhf(nv / om) / nv;
        float e0 = sscl*v0, e1 = sscl*v1, e2 = sscl*v2, e3 = sscl*v3;
        float xy = wsum(x4.x*e0 + x4.y*e1 + x4.z*e2 + x4.w*e3);
        float s2 = wsum(e0*e0 + e1*e1 + e2*e2 + e3*e3);
        float cA = 1.0f + 2.0f*xy + s2;
        float cB = 1.0f - x2;
        float iden = 1.0f / fmaxf(1.0f + 2.0f*xy + x2*s2, 1e-6f);
        float z0 = (cA*x4.x + cB*e0)*iden;
        float z1 = (cA*x4.y + cB*e1)*iden;
        float z2 = (cA*x4.z + cB*e2)*iden;
        float z3 = (cA*x4.w + cB*e3)*iden;
        float zn2 = wsum(z0*z0 + z1*z1 + z2*z2 + z3*z3);
        float zn  = sqrtf(fmaxf(zn2, 1e-12f));
        if (zn > 0.99999f) {
            float ps = 0.99999f / zn;
            z0 *= ps; z1 *= ps; z2 *= ps; z3 *= ps;
            zn2 *= ps * ps;
        }
        float tn = sqrtf(fmaxf(zn2, 1e-12f));
        float tf = artanh_c(tn) / tn;
        ((float4*)(g_t0 + (i * NROW + row) * 128))[lane] =
            make_float4(tf*z0, tf*z1, tf*z2, tf*z3);

        if (i < 3) {
            float4 zn4 = make_float4(z0, z1, z2, z3);
            float nv0, nv1, nv2b, nv3;
            logmap_v(x4, x2, zn4, zn2, nv0, nv1, nv2b, nv3);
            av0 = fmaf(0.9f, av0 - w0 * vc[i][0], w13 * nv0);
            av1 = fmaf(0.9f, av1 - w0 * vc[i][1], w13 * nv1);
            av2 = fmaf(0.9f, av2 - w0 * vc[i][2], w13 * nv2b);
            av3 = fmaf(0.9f, av3 - w0 * vc[i][3], w13 * nv3);
        }
        x4 = make_float4(z0, z1, z2, z3); x2 = zn2;
    }
}

// ---------------------------------------------------------------------------
// KBC: fused MLP.  Block = 128 rows of one iter, 512 threads.
// 4 chunks of 128 W1-cols: GEMM1 (8x4 micro-tile, row-paired b64 operands)
// -> relu h in smem -> GEMM2 paired over k2 (all operands direct b64).
// smem = 213376 B -> 1 block/SM, 16 warps.
// ---------------------------------------------------------------------------
__global__ __launch_bounds__(512, 1)
void kbc_kernel(float* __restrict__ out, const float* __restrict__ W1,
                const float* __restrict__ b1, const float* __restrict__ W2,
                const float* __restrict__ b2)
{
    extern __shared__ float sm[];
    float* sT  = sm;                   // [128 k][132 r]  transposed t0 tile
    float* sW1 = sT + 128 * 132;       // [128 k][128 c]
    float* sH  = sW1 + 128 * 128;      // [128 r][132 k2]
    float* sW2 = sH + 128 * 132;       // [24 s][132 k2]  transposed W2 chunk

    const int tid = threadIdx.x;
    const int i  = blockIdx.x >> 7;            // iter 0..3
    const int rb = blockIdx.x & 127;
    const int rowbase = rb * 128;

    // stage t0 tile transposed: sT[k][r]
    {
        const float* src = g_t0 + (i * NROW + rowbase) * 128;
        for (int idx = tid; idx < 128 * 128; idx += 512) {
            int r = idx >> 7, k = idx & 127;
            sT[k * 132 + r] = src[idx];
        }
    }

    const int tx = tid & 31, ty = tid >> 5;
    const int c0 = tx * 4, r0 = ty * 8;
    const int fl = tid & 127, sq6 = (tid >> 7) * 6;

    ull acc6[6] = {0ull, 0ull, 0ull, 0ull, 0ull, 0ull};   // (even-k2, odd-k2) partials

    for (int nc = 0; nc < 4; ++nc) {
        __syncthreads();   // prev GEMM2 done with sH / prev GEMM1 done with sW1
        for (int idx = tid; idx < 128 * 128; idx += 512) {
            int k = idx >> 7, c = idx & 127;
            sW1[idx] = W1[k * 512 + nc * 128 + c];
        }
        for (int idx = tid; idx < 24 * 128; idx += 512) {
            int s = idx >> 7, k2 = idx & 127;
            sW2[s * 132 + k2] = W2[(nc * 128 + k2) * 24 + s];
        }
        __syncthreads();

        // GEMM1: rows r0..r0+7 (4 pairs) x cols c0..c0+3
        float4 bb = *(const float4*)&b1[nc * 128 + c0];
        ull bc0 = splat2(bb.x), bc1 = splat2(bb.y), bc2 = splat2(bb.z), bc3 = splat2(bb.w);
        ull hacc[4][4];
#pragma unroll
        for (int rp = 0; rp < 4; ++rp) {
            hacc[rp][0] = bc0; hacc[rp][1] = bc1; hacc[rp][2] = bc2; hacc[rp][3] = bc3;
        }
#pragma unroll 2
        for (int k = 0; k < 128; ++k) {
            ull a0, a1, a2, a3;                                  // 4 row-pairs (broadcast)
            lds2u(a0, a1, sT + k * 132 + r0);
            lds2u(a2, a3, sT + k * 132 + r0 + 4);
            float4 wv = *(const float4*)&sW1[k * 128 + c0];      // per-lane
            ull w0 = splat2(wv.x), w1 = splat2(wv.y), w2 = splat2(wv.z), w3 = splat2(wv.w);
            fma2(hacc[0][0], a0, w0); fma2(hacc[0][1], a0, w1); fma2(hacc[0][2], a0, w2); fma2(hacc[0][3], a0, w3);
            fma2(hacc[1][0], a1, w0); fma2(hacc[1][1], a1, w1); fma2(hacc[1][2], a1, w2); fma2(hacc[1][3], a1, w3);
            fma2(hacc[2][0], a2, w0); fma2(hacc[2][1], a2, w1); fma2(hacc[2][2], a2, w2); fma2(hacc[2][3], a2, w3);
            fma2(hacc[3][0], a3, w0); fma2(hacc[3][1], a3, w1); fma2(hacc[3][2], a3, w2); fma2(hacc[3][3], a3, w3);
        }
#pragma unroll
        for (int rp = 0; rp < 4; ++rp) {
            float lo, hi;
            float* d0 = sH + (r0 + 2 * rp) * 132 + c0;
            float* d1 = d0 + 132;
#pragma unroll
            for (int c = 0; c < 4; ++c) {
                unpack2(hacc[rp][c], lo, hi);
                d0[c] = fmaxf(lo, 0.f);
                d1[c] = fmaxf(hi, 0.f);
            }
        }
        __syncthreads();

        // GEMM2: out[fl][sq6..sq6+5] += h[fl][:] @ W2c  (k2-paired, no splats)
#pragma unroll 4
        for (int k2 = 0; k2 < 128; k2 += 4) {
            ull h01, h23;
            lds2u(h01, h23, sH + fl * 132 + k2);                 // conflict-free
#pragma unroll
            for (int s = 0; s < 6; ++s) {
                ull wA, wB;
                lds2u(wA, wB, sW2 + (sq6 + s) * 132 + k2);       // warp-broadcast
                fma2(acc6[s], h01, wA);
                fma2(acc6[s], h23, wB);
            }
        }
    }

    // write predictions: out[(b*96 + i*24 + s)*128 + f]
    const int row_g = rowbase + fl;
    const int b = row_g >> 7;
    const int f = row_g & 127;
#pragma unroll
    for (int s = 0; s < 6; ++s) {
        float lo, hi;
        unpack2(acc6[s], lo, hi);
        int so = sq6 + s;
        out[(b * 96 + i * 24 + so) * 128 + f] = lo + hi + b2[so];
    }
}

// ---------------------------------------------------------------------------
extern "C" void kernel_launch(void* const* d_in, const int* in_sizes, int n_in,
                              void* d_out, int out_size)
{
    const float* trend = (const float*)d_in[0];
    const float* scoar = (const float*)d_in[1];
    const float* sfin  = (const float*)d_in[2];
    const float* resid = (const float*)d_in[3];
    const float* Wt = (const float*)d_in[4];
    const float* bt = (const float*)d_in[5];
    const float* Wc = (const float*)d_in[6];
    const float* bc = (const float*)d_in[7];
    const float* Wf = (const float*)d_in[8];
    const float* bf = (const float*)d_in[9];
    const float* Wr = (const float*)d_in[10];
    const float* br = (const float*)d_in[11];
    const float* alpha = (const float*)d_in[12];
    const float* W1 = (const float*)d_in[13];
    const float* b1 = (const float*)d_in[14];
    const float* W2 = (const float*)d_in[15];
    const float* b2 = (const float*)d_in[16];

    cudaFuncSetAttribute(ka1_kernel, cudaFuncAttributeMaxDynamicSharedMemorySize, 98816);
    cudaFuncSetAttribute(kbc_kernel, cudaFuncAttributeMaxDynamicSharedMemorySize, 213376);

    ka1_kernel<<<1920, 256, 98816>>>(trend, scoar, sfin, resid,
                                     Wt, bt, Wc, bc, Wf, bf, Wr, br);
    ka2_kernel<<<2048, 256>>>(alpha);
    kbc_kernel<<<512, 512, 213376>>>((float*)d_out, W1, b1, W2, b2);
}

// round 10
// speedup vs baseline: 3.1531x; 1.0113x over previous
#include <cuda_runtime.h>
#include <math.h>

#define NROW 16384          // B*F rows
#define MTOT 65536          // NPRED * NROW

// Scratch (static device arrays — allocation-free)
__device__ float g_z[NROW * 15 * 128];   // window embeddings z_0..z_14 per row
__device__ float g_zn2[NROW * 15];       // squared norms of z
__device__ float g_t0[MTOT * 128];       // logmap0(z_next) per (iter,row)

// ---------------------------------------------------------------- helpers
__device__ __forceinline__ float wsum(float v) {
#pragma unroll
    for (int o = 16; o; o >>= 1) v += __shfl_xor_sync(0xffffffffu, v, o);
    return v;
}
__device__ __forceinline__ float artanh_c(float x) {
    x = fminf(fmaxf(x, -1.0f + 1e-7f), 1.0f - 1e-7f);
    return 0.5f * logf((1.0f + x) / (1.0f - x));
}
typedef unsigned long long ull;
__device__ __forceinline__ void fma2(ull& c, ull a, ull b) {
    asm("fma.rn.f32x2 %0, %1, %2, %0;" : "+l"(c) : "l"(a), "l"(b));
}
__device__ __forceinline__ ull splat2(float x) {
    ull r; asm("mov.b64 %0, {%1, %1};" : "=l"(r) : "f"(x)); return r;
}
__device__ __forceinline__ void unpack2(ull v, float& lo, float& hi) {
    asm("mov.b64 {%0, %1}, %2;" : "=f"(lo), "=f"(hi) : "l"(v));
}
// 16B shared load delivering two packed f32 pairs (no movs)
__device__ __forceinline__ void lds2u(ull& a, ull& b, const float* p) {
    unsigned sa = (unsigned)__cvta_generic_to_shared(p);
    asm("ld.shared.v2.b64 {%0,%1}, [%2];" : "=l"(a), "=l"(b) : "r"(sa));
}

// logmap(x, y) -> velocity vector (lane holds 4 of 128 dims); serial version
__device__ __forceinline__ void logmap_v(float4 x4, float x2, float4 y4, float y2,
                                         float& v0, float& v1, float& v2, float& v3)
{
    float xy = wsum(x4.x*y4.x + x4.y*y4.y + x4.z*y4.z + x4.w*y4.w);
    float cA = 1.0f - 2.0f*xy + y2;
    float cB = 1.0f - x2;
    float iden = 1.0f / fmaxf(1.0f - 2.0f*xy + x2*y2, 1e-6f);
    float d0 = (cB*y4.x - cA*x4.x)*iden;
    float d1 = (cB*y4.y - cA*x4.y)*iden;
    float d2 = (cB*y4.z - cA*x4.z)*iden;
    float d3 = (cB*y4.w - cA*x4.w)*iden;
    float n2 = wsum(d0*d0 + d1*d1 + d2*d2 + d3*d3);
    float n  = sqrtf(fmaxf(n2, 1e-12f));
    float fac = fmaxf(cB, 1e-6f) * artanh_c(n) / n;
    v0 = fac*d0; v1 = fac*d1; v2 = fac*d2; v3 = fac*d3;
}

// ---------------------------------------------------------------------------
// KA1: embedding GEMM + expmap0.  Block = (b, segment j of window).
// Warp = 16 f rows (8 packed f-pairs), lane = 4 dims.
// Epilogue: batched (ILP) norm reductions + |z| = tanh(|v|) identity
// (one reduction chain per row instead of two serial ones).
// ---------------------------------------------------------------------------
__global__ __launch_bounds__(256, 2)
void ka1_kernel(const float* __restrict__ trend, const float* __restrict__ scoar,
                const float* __restrict__ sfin,  const float* __restrict__ resid,
                const float* __restrict__ Wt, const float* __restrict__ bt,
                const float* __restrict__ Wc, const float* __restrict__ bc,
                const float* __restrict__ Wf, const float* __restrict__ bff,
                const float* __restrict__ Wr, const float* __restrict__ br)
{
    extern __shared__ float sm[];
    float* sA    = sm;            // [96 k][128 f]
    float* sW    = sA + 12288;    // [96 k][128 d]
    float* sbias = sW + 12288;    // 128

    const int tid = threadIdx.x;
    const int b = blockIdx.x / 15;
    const int j = blockIdx.x - b * 15;
    const int lbase = b * 720 + 360 + j * 24;

    {
        const float* ptrs[4] = {trend, scoar, sfin, resid};
        const float* wptr[4] = {Wt, Wc, Wf, Wr};
#pragma unroll
        for (int st = 0; st < 4; ++st) {
            const float* p = ptrs[st] + lbase * 128;
            for (int idx = tid; idx < 3072; idx += 256) sA[st * 3072 + idx] = p[idx];
            const float* wp = wptr[st];
            for (int idx = tid; idx < 3072; idx += 256) sW[st * 3072 + idx] = wp[idx];
        }
    }
    if (tid < 128) sbias[tid] = bt[tid] + bc[tid] + bff[tid] + br[tid];
    __syncthreads();

    const int w = tid >> 5, lane = tid & 31;
    const int fb = w * 16;

    const float4 bias4 = ((const float4*)sbias)[lane];
    ull bini[4] = { splat2(bias4.x), splat2(bias4.y), splat2(bias4.z), splat2(bias4.w) };
    // acc[fpair][dim] : lo = f even, hi = f odd
    ull acc[8][4];
#pragma unroll
    for (int p = 0; p < 8; ++p)
#pragma unroll
        for (int d = 0; d < 4; ++d) acc[p][d] = bini[d];

    const float4* sW4 = (const float4*)sW;
#pragma unroll 2
    for (int k = 0; k < 96; ++k) {
        float4 wv = sW4[k * 32 + lane];           // per-lane weights, 4 dims
        ull wd0 = splat2(wv.x), wd1 = splat2(wv.y), wd2 = splat2(wv.z), wd3 = splat2(wv.w);
        const float* ab = sA + k * 128 + fb;      // f-contiguous (broadcast)
        ull a0, a1, a2, a3, a4, a5, a6, a7;
        lds2u(a0, a1, ab);
        lds2u(a2, a3, ab + 4);
        lds2u(a4, a5, ab + 8);
        lds2u(a6, a7, ab + 12);
        fma2(acc[0][0], a0, wd0); fma2(acc[0][1], a0, wd1); fma2(acc[0][2], a0, wd2); fma2(acc[0][3], a0, wd3);
        fma2(acc[1][0], a1, wd0); fma2(acc[1][1], a1, wd1); fma2(acc[1][2], a1, wd2); fma2(acc[1][3], a1, wd3);
        fma2(acc[2][0], a2, wd0); fma2(acc[2][1], a2, wd1); fma2(acc[2][2], a2, wd2); fma2(acc[2][3], a2, wd3);
        fma2(acc[3][0], a3, wd0); fma2(acc[3][1], a3, wd1); fma2(acc[3][2], a3, wd2); fma2(acc[3][3], a3, wd3);
        fma2(acc[4][0], a4, wd0); fma2(acc[4][1], a4, wd1); fma2(acc[4][2], a4, wd2); fma2(acc[4][3], a4, wd3);
        fma2(acc[5][0], a5, wd0); fma2(acc[5][1], a5, wd1); fma2(acc[5][2], a5, wd2); fma2(acc[5][3], a5, wd3);
        fma2(acc[6][0], a6, wd0); fma2(acc[6][1], a6, wd1); fma2(acc[6][2], a6, wd2); fma2(acc[6][3], a6, wd3);
        fma2(acc[7][0], a7, wd0); fma2(acc[7][1], a7, wd1); fma2(acc[7][2], a7, wd2); fma2(acc[7][3], a7, wd3);
    }

    // ---- epilogue: batched reductions over 16 rows ----
    float pn[16];
#pragma unroll
    for (int p = 0; p < 8; ++p) {
        float lo0, hi0, lo1, hi1, lo2, hi2, lo3, hi3;
        unpack2(acc[p][0], lo0, hi0);
        unpack2(acc[p][1], lo1, hi1);
        unpack2(acc[p][2], lo2, hi2);
        unpack2(acc[p][3], lo3, hi3);
        pn[2*p]   = lo0*lo0 + lo1*lo1 + lo2*lo2 + lo3*lo3;
        pn[2*p+1] = hi0*hi0 + hi1*hi1 + hi2*hi2 + hi3*hi3;
    }
#pragma unroll
    for (int o = 16; o; o >>= 1)
#pragma unroll
        for (int r = 0; r < 16; ++r)
            pn[r] += __shfl_xor_sync(0xffffffffu, pn[r], o);

    const int rowb = b * 128 + fb;
#pragma unroll
    for (int p = 0; p < 8; ++p) {
        float v[2][4];
        unpack2(acc[p][0], v[0][0], v[1][0]);
        unpack2(acc[p][1], v[0][1], v[1][1]);
        unpack2(acc[p][2], v[0][2], v[1][2]);
        unpack2(acc[p][3], v[0][3], v[1][3]);
#pragma unroll
        for (int e = 0; e < 2; ++e) {
            float n2 = pn[2*p + e];
            float n  = sqrtf(fmaxf(n2, 1e-12f));
            float t  = tanhf(n);
            float tc = fminf(t, 0.99999f);     // |z| = tanh(n); project clamps it
            float scl = tc / n;
            int row = rowb + 2 * p + e;
            ((float4*)(g_z + (row * 15 + j) * 128))[lane] =
                make_float4(scl*v[e][0], scl*v[e][1], scl*v[e][2], scl*v[e][3]);
            if (lane == 0) g_zn2[row * 15 + j] = tc * tc;
        }
    }
}

// ---------------------------------------------------------------------------
// KA2: 4-step recurrence.  Warp = one (b,f) row; lane = 4 dims.
// The 14 window logmaps are independent -> batched (ILP) reductions.
// Only the 4 prediction steps remain serial.
// ---------------------------------------------------------------------------
__global__ __launch_bounds__(256)
void ka2_kernel(const float* __restrict__ alphap)
{
    const int w = threadIdx.x >> 5, lane = threadIdx.x & 31;
    const int row = blockIdx.x * 8 + w;
    const float alpha = alphap[0];

    float S = 0.0f, p = 1.0f;
#pragma unroll
    for (int e = 0; e < 14; ++e) { S += p; p *= 0.9f; }
    const float w13 = 1.0f / S;
    float w0 = w13;
#pragma unroll
    for (int e = 0; e < 13; ++e) w0 *= 0.9f;
    const float inv09 = 1.0f / 0.9f;

    const float* zp = g_z   + row * 15 * 128;
    const float* np = g_zn2 + row * 15;

    // load all window z's (independent LDGs, high MLP)
    float4 z[15]; float zn[15];
#pragma unroll
    for (int jj = 0; jj < 15; ++jj) {
        z[jj]  = ((const float4*)(zp + jj * 128))[lane];
        zn[jj] = __ldg(np + jj);
    }

    // batched dot products x_j . x_{j+1}
    float px[14];
#pragma unroll
    for (int jj = 0; jj < 14; ++jj)
        px[jj] = z[jj].x*z[jj+1].x + z[jj].y*z[jj+1].y +
                 z[jj].z*z[jj+1].z + z[jj].w*z[jj+1].w;
#pragma unroll
    for (int o = 16; o; o >>= 1)
#pragma unroll
        for (int jj = 0; jj < 14; ++jj)
            px[jj] += __shfl_xor_sync(0xffffffffu, px[jj], o);

    // batched difference vectors d_j = mobius_add(-x, y), partial norms
    float d[14][4]; float pn[14];
#pragma unroll
    for (int jj = 0; jj < 14; ++jj) {
        float x2 = zn[jj], y2 = zn[jj+1], xy = px[jj];
        float cA = 1.0f - 2.0f*xy + y2;
        float cB = 1.0f - x2;
        float iden = 1.0f / fmaxf(1.0f - 2.0f*xy + x2*y2, 1e-6f);
        d[jj][0] = (cB*z[jj+1].x - cA*z[jj].x)*iden;
        d[jj][1] = (cB*z[jj+1].y - cA*z[jj].y)*iden;
        d[jj][2] = (cB*z[jj+1].z - cA*z[jj].z)*iden;
        d[jj][3] = (cB*z[jj+1].w - cA*z[jj].w)*iden;
        pn[jj] = d[jj][0]*d[jj][0] + d[jj][1]*d[jj][1] +
                 d[jj][2]*d[jj][2] + d[jj][3]*d[jj][3];
    }
#pragma unroll
    for (int o = 16; o; o >>= 1)
#pragma unroll
        for (int jj = 0; jj < 14; ++jj)
            pn[jj] += __shfl_xor_sync(0xffffffffu, pn[jj], o);

    // weighted average of velocities; cache first 3 velocities for sliding
    float av0 = 0.f, av1 = 0.f, av2 = 0.f, av3 = 0.f;
    float vc[3][4];
    float wcur = w0;
#pragma unroll
    for (int jj = 0; jj < 14; ++jj) {
        float n = sqrtf(fmaxf(pn[jj], 1e-12f));
        float fac = fmaxf(1.0f - zn[jj], 1e-6f) * artanh_c(n) / n;
        float v0 = fac*d[jj][0], v1 = fac*d[jj][1], v2 = fac*d[jj][2], v3 = fac*d[jj][3];
        if (jj < 3) { vc[jj][0] = v0; vc[jj][1] = v1; vc[jj][2] = v2; vc[jj][3] = v3; }
        av0 = fmaf(wcur, v0, av0); av1 = fmaf(wcur, v1, av1);
        av2 = fmaf(wcur, v2, av2); av3 = fmaf(wcur, v3, av3);
        wcur *= inv09;
    }

    float4 x4 = z[14];
    float  x2 = zn[14];

#pragma unroll
    for (int i = 0; i < 4; ++i) {
        float v0 = alpha * av0, v1 = alpha * av1, v2 = alpha * av2, v3 = alpha * av3;
        float nv2 = wsum(v0*v0 + v1*v1 + v2*v2 + v3*v3);
        float nv  = sqrtf(fmaxf(nv2, 1e-12f));
        float om  = fmaxf(1.0f - x2, 1e-6f);
        float sscl = tanhf(nv / om) / nv;
        float e0 = sscl*v0, e1 = sscl*v1, e2 = sscl*v2, e3 = sscl*v3;
        float xy = wsum(x4.x*e0 + x4.y*e1 + x4.z*e2 + x4.w*e3);
        float s2 = wsum(e0*e0 + e1*e1 + e2*e2 + e3*e3);
        float cA = 1.0f + 2.0f*xy + s2;
        float cB = 1.0f - x2;
        float iden = 1.0f / fmaxf(1.0f + 2.0f*xy + x2*s2, 1e-6f);
        float z0 = (cA*x4.x + cB*e0)*iden;
        float z1 = (cA*x4.y + cB*e1)*iden;
        float z2 = (cA*x4.z + cB*e2)*iden;
        float z3 = (cA*x4.w + cB*e3)*iden;
        float zn2 = wsum(z0*z0 + z1*z1 + z2*z2 + z3*z3);
        float znn = sqrtf(fmaxf(zn2, 1e-12f));
        if (znn > 0.99999f) {
            float ps = 0.99999f / znn;
            z0 *= ps; z1 *= ps; z2 *= ps; z3 *= ps;
            zn2 *= ps * ps;
        }
        float tn = sqrtf(fmaxf(zn2, 1e-12f));
        float tf = artanh_c(tn) / tn;
        ((float4*)(g_t0 + (i * NROW + row) * 128))[lane] =
            make_float4(tf*z0, tf*z1, tf*z2, tf*z3);

        if (i < 3) {
            float4 zn4 = make_float4(z0, z1, z2, z3);
            float nv0, nv1, nv2b, nv3;
            logmap_v(x4, x2, zn4, zn2, nv0, nv1, nv2b, nv3);
            av0 = fmaf(0.9f, av0 - w0 * vc[i][0], w13 * nv0);
            av1 = fmaf(0.9f, av1 - w0 * vc[i][1], w13 * nv1);
            av2 = fmaf(0.9f, av2 - w0 * vc[i][2], w13 * nv2b);
            av3 = fmaf(0.9f, av3 - w0 * vc[i][3], w13 * nv3);
        }
        x4 = make_float4(z0, z1, z2, z3); x2 = zn2;
    }
}

// ---------------------------------------------------------------------------
// KBC: fused MLP.  Block = 128 rows of one iter, 512 threads.
// (unchanged from R8 — carried the win)
// ---------------------------------------------------------------------------
__global__ __launch_bounds__(512, 1)
void kbc_kernel(float* __restrict__ out, const float* __restrict__ W1,
                const float* __restrict__ b1, const float* __restrict__ W2,
                const float* __restrict__ b2)
{
    extern __shared__ float sm[];
    float* sT  = sm;                   // [128 k][132 r]  transposed t0 tile
    float* sW1 = sT + 128 * 132;       // [128 k][128 c]
    float* sH  = sW1 + 128 * 128;      // [128 r][132 k2]
    float* sW2 = sH + 128 * 132;       // [24 s][132 k2]  transposed W2 chunk

    const int tid = threadIdx.x;
    const int i  = blockIdx.x >> 7;            // iter 0..3
    const int rb = blockIdx.x & 127;
    const int rowbase = rb * 128;

    {
        const float* src = g_t0 + (i * NROW + rowbase) * 128;
        for (int idx = tid; idx < 128 * 128; idx += 512) {
            int r = idx >> 7, k = idx & 127;
            sT[k * 132 + r] = src[idx];
        }
    }

    const int tx = tid & 31, ty = tid >> 5;
    const int c0 = tx * 4, r0 = ty * 8;
    const int fl = tid & 127, sq6 = (tid >> 7) * 6;

    ull acc6[6] = {0ull, 0ull, 0ull, 0ull, 0ull, 0ull};

    for (int nc = 0; nc < 4; ++nc) {
        __syncthreads();
        for (int idx = tid; idx < 128 * 128; idx += 512) {
            int k = idx >> 7, c = idx & 127;
            sW1[idx] = W1[k * 512 + nc * 128 + c];
        }
        for (int idx = tid; idx < 24 * 128; idx += 512) {
            int s = idx >> 7, k2 = idx & 127;
            sW2[s * 132 + k2] = W2[(nc * 128 + k2) * 24 + s];
        }
        __syncthreads();

        float4 bb = *(const float4*)&b1[nc * 128 + c0];
        ull bc0 = splat2(bb.x), bc1 = splat2(bb.y), bc2 = splat2(bb.z), bc3 = splat2(bb.w);
        ull hacc[4][4];
#pragma unroll
        for (int rp = 0; rp < 4; ++rp) {
            hacc[rp][0] = bc0; hacc[rp][1] = bc1; hacc[rp][2] = bc2; hacc[rp][3] = bc3;
        }
#pragma unroll 2
        for (int k = 0; k < 128; ++k) {
            ull a0, a1, a2, a3;
            lds2u(a0, a1, sT + k * 132 + r0);
            lds2u(a2, a3, sT + k * 132 + r0 + 4);
            float4 wv = *(const float4*)&sW1[k * 128 + c0];
            ull w0 = splat2(wv.x), w1 = splat2(wv.y), w2 = splat2(wv.z), w3 = splat2(wv.w);
            fma2(hacc[0][0], a0, w0); fma2(hacc[0][1], a0, w1); fma2(hacc[0][2], a0, w2); fma2(hacc[0][3], a0, w3);
            fma2(hacc[1][0], a1, w0); fma2(hacc[1][1], a1, w1); fma2(hacc[1][2], a1, w2); fma2(hacc[1][3], a1, w3);
            fma2(hacc[2][0], a2, w0); fma2(hacc[2][1], a2, w1); fma2(hacc[2][2], a2, w2); fma2(hacc[2][3], a2, w3);
            fma2(hacc[3][0], a3, w0); fma2(hacc[3][1], a3, w1); fma2(hacc[3][2], a3, w2); fma2(hacc[3][3], a3, w3);
        }
#pragma unroll
        for (int rp = 0; rp < 4; ++rp) {
            float lo, hi;
            float* d0 = sH + (r0 + 2 * rp) * 132 + c0;
            float* d1 = d0 + 132;
#pragma unroll
            for (int c = 0; c < 4; ++c) {
                unpack2(hacc[rp][c], lo, hi);
                d0[c] = fmaxf(lo, 0.f);
                d1[c] = fmaxf(hi, 0.f);
            }
        }
        __syncthreads();

#pragma unroll 4
        for (int k2 = 0; k2 < 128; k2 += 4) {
            ull h01, h23;
            lds2u(h01, h23, sH + fl * 132 + k2);
#pragma unroll
            for (int s = 0; s < 6; ++s) {
                ull wA, wB;
                lds2u(wA, wB, sW2 + (sq6 + s) * 132 + k2);
                fma2(acc6[s], h01, wA);
                fma2(acc6[s], h23, wB);
            }
        }
    }

    const int row_g = rowbase + fl;
    const int b = row_g >> 7;
    const int f = row_g & 127;
#pragma unroll
    for (int s = 0; s < 6; ++s) {
        float lo, hi;
        unpack2(acc6[s], lo, hi);
        int so = sq6 + s;
        out[(b * 96 + i * 24 + so) * 128 + f] = lo + hi + b2[so];
    }
}

// ---------------------------------------------------------------------------
extern "C" void kernel_launch(void* const* d_in, const int* in_sizes, int n_in,
                              void* d_out, int out_size)
{
    const float* trend = (const float*)d_in[0];
    const float* scoar = (const float*)d_in[1];
    const float* sfin  = (const float*)d_in[2];
    const float* resid = (const float*)d_in[3];
    const float* Wt = (const float*)d_in[4];
    const float* bt = (const float*)d_in[5];
    const float* Wc = (const float*)d_in[6];
    const float* bc = (const float*)d_in[7];
    const float* Wf = (const float*)d_in[8];
    const float* bf = (const float*)d_in[9];
    const float* Wr = (const float*)d_in[10];
    const float* br = (const float*)d_in[11];
    const float* alpha = (const float*)d_in[12];
    const float* W1 = (const float*)d_in[13];
    const float* b1 = (const float*)d_in[14];
    const float* W2 = (const float*)d_in[15];
    const float* b2 = (const float*)d_in[16];

    cudaFuncSetAttribute(ka1_kernel, cudaFuncAttributeMaxDynamicSharedMemorySize, 98816);
    cudaFuncSetAttribute(kbc_kernel, cudaFuncAttributeMaxDynamicSharedMemorySize, 213376);

    ka1_kernel<<<1920, 256, 98816>>>(trend, scoar, sfin, resid,
                                     Wt, bt, Wc, bc, Wf, bf, Wr, br);
    ka2_kernel<<<2048, 256>>>(alpha);
    kbc_kernel<<<512, 512, 213376>>>((float*)d_out, W1, b1, W2, b2);
}